// round 8
// baseline (speedup 1.0000x reference)
#include <cuda_runtime.h>

// TaylorActivation: out = Horner(x; c[0..8]), elementwise over 512x65536 fp32.
// HBM-bound stream: 128 MiB in + 128 MiB out. Floor = 32us @ 8TB/s.
//
// R7: 8x float4 per thread, all loads front-batched (MLP_p1=8) to hide
//     DRAM latency deeper. Single kernel node. Default cache ops
//     (hints measured neutral in R4).

__global__ void __launch_bounds__(256)
taylor_kernel(const float4* __restrict__ x,
              const float* __restrict__ w,
              float4* __restrict__ out)
{
    int base = blockIdx.x * (256 * 8) + threadIdx.x;

    // Front-batched independent loads (MLP_p1 = 8, 32 sectors in flight/thread-group).
    float4 v0 = x[base + 0 * 256];
    float4 v1 = x[base + 1 * 256];
    float4 v2 = x[base + 2 * 256];
    float4 v3 = x[base + 3 * 256];
    float4 v4 = x[base + 4 * 256];
    float4 v5 = x[base + 5 * 256];
    float4 v6 = x[base + 6 * 256];
    float4 v7 = x[base + 7 * 256];

    // 9 coefficients via 3 broadcast loads (L1-resident after first warp).
    const float4 wa = __ldg((const float4*)&w[0]);  // c0..c3
    const float4 wb = __ldg((const float4*)&w[4]);  // c4..c7
    const float  c8 = __ldg(&w[8]);
    const float c0 = wa.x, c1 = wa.y, c2 = wa.z, c3 = wa.w;
    const float c4 = wb.x, c5 = wb.y, c6 = wb.z, c7 = wb.w;

    // Horner per float4, computed pairwise to bound register pressure:
    // each POLY consumes its v and immediately stores.
#define POLY(vv, slot)                                                        \
    {                                                                         \
        float4 r;                                                             \
        r.x = fmaf(c8, vv.x, c7); r.y = fmaf(c8, vv.y, c7);                   \
        r.z = fmaf(c8, vv.z, c7); r.w = fmaf(c8, vv.w, c7);                   \
        r.x = fmaf(r.x, vv.x, c6); r.y = fmaf(r.y, vv.y, c6);                 \
        r.z = fmaf(r.z, vv.z, c6); r.w = fmaf(r.w, vv.w, c6);                 \
        r.x = fmaf(r.x, vv.x, c5); r.y = fmaf(r.y, vv.y, c5);                 \
        r.z = fmaf(r.z, vv.z, c5); r.w = fmaf(r.w, vv.w, c5);                 \
        r.x = fmaf(r.x, vv.x, c4); r.y = fmaf(r.y, vv.y, c4);                 \
        r.z = fmaf(r.z, vv.z, c4); r.w = fmaf(r.w, vv.w, c4);                 \
        r.x = fmaf(r.x, vv.x, c3); r.y = fmaf(r.y, vv.y, c3);                 \
        r.z = fmaf(r.z, vv.z, c3); r.w = fmaf(r.w, vv.w, c3);                 \
        r.x = fmaf(r.x, vv.x, c2); r.y = fmaf(r.y, vv.y, c2);                 \
        r.z = fmaf(r.z, vv.z, c2); r.w = fmaf(r.w, vv.w, c2);                 \
        r.x = fmaf(r.x, vv.x, c1); r.y = fmaf(r.y, vv.y, c1);                 \
        r.z = fmaf(r.z, vv.z, c1); r.w = fmaf(r.w, vv.w, c1);                 \
        r.x = fmaf(r.x, vv.x, c0); r.y = fmaf(r.y, vv.y, c0);                 \
        r.z = fmaf(r.z, vv.z, c0); r.w = fmaf(r.w, vv.w, c0);                 \
        out[base + slot * 256] = r;                                           \
    }

    POLY(v0, 0) POLY(v1, 1) POLY(v2, 2) POLY(v3, 3)
    POLY(v4, 4) POLY(v5, 5) POLY(v6, 6) POLY(v7, 7)
#undef POLY
}

extern "C" void kernel_launch(void* const* d_in, const int* in_sizes, int n_in,
                              void* d_out, int out_size)
{
    const float* x = (const float*)d_in[0];   // (512, 65536) fp32
    const float* w = (const float*)d_in[1];   // (9, 1) fp32
    float* out = (float*)d_out;

    int n = in_sizes[0];          // 33554432
    int n4 = n / 4;               // 8388608 float4
    int blocks = n4 / (256 * 8);  // 4096 (exact)

    taylor_kernel<<<blocks, 256>>>(
        (const float4*)x, w, (float4*)out);
}

// round 9
// speedup vs baseline: 1.0185x; 1.0185x over previous
#include <cuda_runtime.h>

// TaylorActivation: out = Horner(x; c[0..8]), elementwise over 512x65536 fp32.
// HBM/LTS-bound stream: 128 MiB in + 128 MiB out (~6300 B/cyc LTS chip cap).
//
// R8: best measured memory body (R2): 4x float4/thread, 256 thr, 8192 blocks,
//     DEFAULT cache ops (hints measured -0.7us in R4), coeffs via 3 vectorized
//     broadcast LDGs (no memcpy node in graph).

__global__ void __launch_bounds__(256)
taylor_kernel(const float4* __restrict__ x,
              const float* __restrict__ w,
              float4* __restrict__ out)
{
    int base = blockIdx.x * (256 * 4) + threadIdx.x;

    // Front-batched independent loads (MLP_p1 = 4).
    float4 v0 = x[base + 0 * 256];
    float4 v1 = x[base + 1 * 256];
    float4 v2 = x[base + 2 * 256];
    float4 v3 = x[base + 3 * 256];

    // 9 coefficients via 3 broadcast loads (L1-resident after first warp).
    const float4 wa = __ldg((const float4*)&w[0]);  // c0..c3
    const float4 wb = __ldg((const float4*)&w[4]);  // c4..c7
    const float  c8 = __ldg(&w[8]);
    const float c0 = wa.x, c1 = wa.y, c2 = wa.z, c3 = wa.w;
    const float c4 = wb.x, c5 = wb.y, c6 = wb.z, c7 = wb.w;

    float4 r0, r1, r2, r3;
    r0.x = r0.y = r0.z = r0.w = c8;
    r1.x = r1.y = r1.z = r1.w = c8;
    r2.x = r2.y = r2.z = r2.w = c8;
    r3.x = r3.y = r3.z = r3.w = c8;

#define STEP(ck)                                                             \
    r0.x = fmaf(r0.x, v0.x, ck); r0.y = fmaf(r0.y, v0.y, ck);                \
    r0.z = fmaf(r0.z, v0.z, ck); r0.w = fmaf(r0.w, v0.w, ck);                \
    r1.x = fmaf(r1.x, v1.x, ck); r1.y = fmaf(r1.y, v1.y, ck);                \
    r1.z = fmaf(r1.z, v1.z, ck); r1.w = fmaf(r1.w, v1.w, ck);                \
    r2.x = fmaf(r2.x, v2.x, ck); r2.y = fmaf(r2.y, v2.y, ck);                \
    r2.z = fmaf(r2.z, v2.z, ck); r2.w = fmaf(r2.w, v2.w, ck);                \
    r3.x = fmaf(r3.x, v3.x, ck); r3.y = fmaf(r3.y, v3.y, ck);                \
    r3.z = fmaf(r3.z, v3.z, ck); r3.w = fmaf(r3.w, v3.w, ck);

    STEP(c7) STEP(c6) STEP(c5) STEP(c4)
    STEP(c3) STEP(c2) STEP(c1) STEP(c0)
#undef STEP

    out[base + 0 * 256] = r0;
    out[base + 1 * 256] = r1;
    out[base + 2 * 256] = r2;
    out[base + 3 * 256] = r3;
}

extern "C" void kernel_launch(void* const* d_in, const int* in_sizes, int n_in,
                              void* d_out, int out_size)
{
    const float* x = (const float*)d_in[0];   // (512, 65536) fp32
    const float* w = (const float*)d_in[1];   // (9, 1) fp32
    float* out = (float*)d_out;

    int n = in_sizes[0];          // 33554432
    int n4 = n / 4;               // 8388608 float4
    int blocks = n4 / (256 * 4);  // 8192 (exact)

    taylor_kernel<<<blocks, 256>>>(
        (const float4*)x, w, (float4*)out);
}

// round 10
// speedup vs baseline: 1.0530x; 1.0338x over previous
#include <cuda_runtime.h>
#include <cstdint>

// TaylorActivation: out = Horner(x; c[0..8]), elementwise over 512x65536 fp32.
// HBM/LTS-bound stream: 128 MiB in + 128 MiB out.
//
// R9: R8 memory body (4x float4/thread, front-batched, default cache ops)
//     + packed fma.rn.f32x2 (FFMA2) for the Horner chain — halves FMA issue
//     count (only reachable via PTX; ptxas never auto-fuses).

__device__ __forceinline__ uint64_t pack2(float lo, float hi) {
    uint64_t r;
    asm("mov.b64 %0, {%1, %2};" : "=l"(r) : "f"(lo), "f"(hi));
    return r;
}

__device__ __forceinline__ void unpack2(uint64_t v, float& lo, float& hi) {
    asm("mov.b64 {%0, %1}, %2;" : "=f"(lo), "=f"(hi) : "l"(v));
}

__device__ __forceinline__ uint64_t fma2(uint64_t a, uint64_t b, uint64_t c) {
    uint64_t d;
    asm("fma.rn.f32x2 %0, %1, %2, %3;" : "=l"(d) : "l"(a), "l"(b), "l"(c));
    return d;
}

__global__ void __launch_bounds__(256)
taylor_kernel(const float4* __restrict__ x,
              const float* __restrict__ w,
              float4* __restrict__ out)
{
    int base = blockIdx.x * (256 * 4) + threadIdx.x;

    // Front-batched independent loads (MLP_p1 = 4).
    float4 v0 = x[base + 0 * 256];
    float4 v1 = x[base + 1 * 256];
    float4 v2 = x[base + 2 * 256];
    float4 v3 = x[base + 3 * 256];

    // 9 coefficients via 3 broadcast loads (L1-resident after first warp).
    const float4 wa = __ldg((const float4*)&w[0]);  // c0..c3
    const float4 wb = __ldg((const float4*)&w[4]);  // c4..c7
    const float  c8 = __ldg(&w[8]);

    // Broadcast-packed coefficient pairs (ck, ck).
    const uint64_t p0 = pack2(wa.x, wa.x), p1 = pack2(wa.y, wa.y);
    const uint64_t p2 = pack2(wa.z, wa.z), p3 = pack2(wa.w, wa.w);
    const uint64_t p4 = pack2(wb.x, wb.x), p5 = pack2(wb.y, wb.y);
    const uint64_t p6 = pack2(wb.z, wb.z), p7 = pack2(wb.w, wb.w);
    const uint64_t p8 = pack2(c8, c8);

    // Packed operand lanes: (x,y) and (z,w) of each float4.
    uint64_t a0 = pack2(v0.x, v0.y), b0 = pack2(v0.z, v0.w);
    uint64_t a1 = pack2(v1.x, v1.y), b1 = pack2(v1.z, v1.w);
    uint64_t a2 = pack2(v2.x, v2.y), b2 = pack2(v2.z, v2.w);
    uint64_t a3 = pack2(v3.x, v3.y), b3 = pack2(v3.z, v3.w);

    uint64_t ra0 = p8, rb0 = p8;
    uint64_t ra1 = p8, rb1 = p8;
    uint64_t ra2 = p8, rb2 = p8;
    uint64_t ra3 = p8, rb3 = p8;

#define STEP(pk)                                    \
    ra0 = fma2(ra0, a0, pk); rb0 = fma2(rb0, b0, pk); \
    ra1 = fma2(ra1, a1, pk); rb1 = fma2(rb1, b1, pk); \
    ra2 = fma2(ra2, a2, pk); rb2 = fma2(rb2, b2, pk); \
    ra3 = fma2(ra3, a3, pk); rb3 = fma2(rb3, b3, pk);

    STEP(p7) STEP(p6) STEP(p5) STEP(p4)
    STEP(p3) STEP(p2) STEP(p1) STEP(p0)
#undef STEP

    float4 r;
    unpack2(ra0, r.x, r.y); unpack2(rb0, r.z, r.w); out[base + 0 * 256] = r;
    unpack2(ra1, r.x, r.y); unpack2(rb1, r.z, r.w); out[base + 1 * 256] = r;
    unpack2(ra2, r.x, r.y); unpack2(rb2, r.z, r.w); out[base + 2 * 256] = r;
    unpack2(ra3, r.x, r.y); unpack2(rb3, r.z, r.w); out[base + 3 * 256] = r;
}

extern "C" void kernel_launch(void* const* d_in, const int* in_sizes, int n_in,
                              void* d_out, int out_size)
{
    const float* x = (const float*)d_in[0];   // (512, 65536) fp32
    const float* w = (const float*)d_in[1];   // (9, 1) fp32
    float* out = (float*)d_out;

    int n = in_sizes[0];          // 33554432
    int n4 = n / 4;               // 8388608 float4
    int blocks = n4 / (256 * 4);  // 8192 (exact)

    taylor_kernel<<<blocks, 256>>>(
        (const float4*)x, w, (float4*)out);
}